// round 11
// baseline (speedup 1.0000x reference)
#include <cuda_runtime.h>
#include <cuda_bf16.h>
#include <mma.h>
#include <cstdint>

// ManeuverHead on GB300 — 2 kernels.
//  k_front: persistent fused front end (grid barriers): init + masked scans +
//           boundary cbase + scatter + w1 tile-major bf16 repack + w2 fp32 pad.
//  k_main : 1024 blocks x 32 slots x 128 threads, launch_bounds(128,5).
//           Dedup'd global mini-GEMM + node GEMM (bf16 WMMA, fb from global
//           tile-major w1), fp32 relu+b1+GP, tf32 layer 2 (fb2 from global),
//           masked output. smem ~28 KB -> 5 blocks/SM.
// N=262144, B=4096, D=128, G=8, R=7.

#define NNODES   262144
#define NB       4096
#define GG       8
#define RR       7
#define NSLOTS   (NB * GG)
#define NEGV     (-1e9f)
#define FGRID    256

using namespace nvcuda;

// ---------------- device scratch ------------------------------------------
__device__ int            d_blockSums[FGRID];
__device__ int            d_blockOff[FGRID];
__device__ int            d_cbase[NB];
__device__ int            d_slotNode[NSLOTS];
__device__ __nv_bfloat16  d_w1t[32768];    // w1 [256][128] bf16, 16x16 TILE-MAJOR:
                                           // tile (kt,nt) at (kt*8+nt)*256
__device__ float          d_w2f[2048];     // w2 padded fp32 [128][16] (cols 7..15 = 0)
__device__ unsigned int   g_cnt;           // zero-init
__device__ volatile unsigned int g_gen;    // zero-init

// ---------------- K1: fused front end --------------------------------------
__global__ void __launch_bounds__(256)
k_front(const int* __restrict__ mask, const int* __restrict__ batch,
        const float* __restrict__ w1, const float* __restrict__ w2) {
    int t = threadIdx.x, bid = blockIdx.x;
    int lane = t & 31, warp = t >> 5;
    int gid = bid * 256 + t;

    __shared__ int ws[8];
    __shared__ unsigned int s_gen;
    __shared__ int s_lead;

    // ---- P0: aux init + weight staging ----
    if (gid < NSLOTS) d_slotNode[gid] = -1;
    if (gid < 32768) {
        int kk = gid >> 7, n = gid & 127;
        int dst = ((kk >> 4) * 8 + (n >> 4)) * 256 + (kk & 15) * 16 + (n & 15);
        d_w1t[dst] = __float2bfloat16(w1[gid]);
    }
    if (gid < 2048) {
        int j = gid >> 4, r = gid & 15;
        d_w2f[gid] = (r < RR) ? w2[j * RR + r] : 0.f;
    }

    // ---- P0: block scan of masked flags ----
    int4 m = ((const int4*)mask)[gid];
    int4 b = ((const int4*)batch)[gid];
    int g0 = m.x != 0, g1 = m.y != 0, g2 = m.z != 0, g3 = m.w != 0;
    int s = g0 + g1 + g2 + g3;
    int inc = s;
#pragma unroll
    for (int o = 1; o < 32; o <<= 1) {
        int v = __shfl_up_sync(~0u, inc, o);
        if (lane >= o) inc += v;
    }
    if (lane == 31) ws[warp] = inc;
    __syncthreads();
    if (warp == 0 && lane < 8) {
        int v = ws[lane], iv = v;
#pragma unroll
        for (int o = 1; o < 8; o <<= 1) {
            int x = __shfl_up_sync(0xffu, iv, o);
            if (lane >= o) iv += x;
        }
        ws[lane] = iv - v;
        if (lane == 7) d_blockSums[bid] = iv;
    }
    __syncthreads();
    int lexcl = ws[warp] + (inc - s);

    // ---- BAR1: leader scans blockSums -> blockOff ----
    __threadfence();
    __syncthreads();
    if (t == 0) {
        s_gen = g_gen;
        unsigned int a = atomicAdd(&g_cnt, 1u);
        s_lead = (a == (unsigned)gridDim.x - 1u);
    }
    __syncthreads();
    if (s_lead) {
        __threadfence();
        int v = d_blockSums[t];
        int iv = v;
#pragma unroll
        for (int o = 1; o < 32; o <<= 1) {
            int x = __shfl_up_sync(~0u, iv, o);
            if (lane >= o) iv += x;
        }
        if (lane == 31) ws[warp] = iv;
        __syncthreads();
        if (warp == 0 && lane < 8) {
            int v2 = ws[lane], iv2 = v2;
#pragma unroll
            for (int o = 1; o < 8; o <<= 1) {
                int x = __shfl_up_sync(0xffu, iv2, o);
                if (lane >= o) iv2 += x;
            }
            ws[lane] = iv2 - v2;
        }
        __syncthreads();
        d_blockOff[t] = ws[warp] + (iv - v);
        __threadfence();
        __syncthreads();
        if (t == 0) {
            *(volatile unsigned int*)&g_cnt = 0u;
            __threadfence();
            g_gen = s_gen + 1u;
        }
    } else {
        if (t == 0) {
            while (g_gen == s_gen) __nanosleep(64);
            __threadfence();
        }
        __syncthreads();
    }

    // ---- P2: boundary nodes write cbase ----
    int pe0 = d_blockOff[bid] + lexcl;
    int pw = __shfl_up_sync(~0u, b.w, 1);
    int prevb = (lane == 0) ? ((gid > 0) ? batch[gid * 4 - 1] : -1) : pw;
    {
        int pe = pe0;
        if (b.x != prevb) d_cbase[b.x] = pe;  pe += g0;
        if (b.y != b.x)   d_cbase[b.y] = pe;  pe += g1;
        if (b.z != b.y)   d_cbase[b.z] = pe;  pe += g2;
        if (b.w != b.z)   d_cbase[b.w] = pe;
    }

    // ---- BAR2 ----
    __threadfence();
    __syncthreads();
    if (t == 0) {
        s_gen = g_gen;
        unsigned int a = atomicAdd(&g_cnt, 1u);
        s_lead = (a == (unsigned)gridDim.x - 1u);
    }
    __syncthreads();
    if (s_lead) {
        if (t == 0) {
            *(volatile unsigned int*)&g_cnt = 0u;
            __threadfence();
            g_gen = s_gen + 1u;
        }
        __syncthreads();
    } else {
        if (t == 0) {
            while (g_gen == s_gen) __nanosleep(64);
            __threadfence();
        }
        __syncthreads();
    }

    // ---- P3: scatter ----
    int base = gid * 4;
    int pre = pe0;
    if (g0) { int r = pre - d_cbase[b.x]; if (r < GG) d_slotNode[b.x * GG + r] = base;     pre++; }
    if (g1) { int r = pre - d_cbase[b.y]; if (r < GG) d_slotNode[b.y * GG + r] = base + 1; pre++; }
    if (g2) { int r = pre - d_cbase[b.z]; if (r < GG) d_slotNode[b.z * GG + r] = base + 2; pre++; }
    if (g3) { int r = pre - d_cbase[b.w]; if (r < GG) d_slotNode[b.w * GG + r] = base + 3; }
}

// ---------------- K2: main -------------------------------------------------
// 1024 blocks x 32 slots (4 batches), 128 threads, 4 warps.
// Warp w: n-tiles {2w, 2w+1}; node GEMM m-tiles 0..1, mini-GEMM m-tile 0.
// smem (bytes):
//   union @0 size 16896:
//     As bf16 [32][136] @0     (8704)    node-feature A tile
//     Ag bf16 [16][136] @8704  (4352)    global A tile (rows 0..3 real, rest 0)
//     H32 fp32 [32][132] @0    (16896)   aliases As/Ag after layer 1
//   GP  fp32 [16][132] @16896  (8448)
//   Sc  fp32 [32][16]  @25344  (2048)
//   nodeS int [32]     @27392  (128)
//   b1s fp32 [128]     @27520  (512)
//   b2s fp32 [8]       @28032  (32)
#define OFF_AG    8704
#define OFF_GP    16896
#define OFF_SC    25344
#define OFF_NODE  27392
#define OFF_B1    27520
#define OFF_B2    28032
#define MAIN_SMEM_BYTES 28064

__global__ void __launch_bounds__(128, 5)
k_main(const float* __restrict__ nf,
       const float* __restrict__ gf,
       const float* __restrict__ b1,
       const float* __restrict__ b2,
       const int* __restrict__ mvm,
       float* __restrict__ out) {
    extern __shared__ __align__(16) unsigned char sm[];
    __nv_bfloat16* As   = (__nv_bfloat16*)sm;                 // ldm 136
    __nv_bfloat16* Ag   = (__nv_bfloat16*)(sm + OFF_AG);      // ldm 136
    float*         H32  = (float*)sm;                         // ldm 132
    float*         GP   = (float*)(sm + OFF_GP);              // ldm 132
    float*         Sc   = (float*)(sm + OFF_SC);              // ldm 16
    int*           nodeS= (int*)(sm + OFF_NODE);
    float*         b1s  = (float*)(sm + OFF_B1);
    float*         b2s  = (float*)(sm + OFF_B2);

    int t = threadIdx.x, w = t >> 5;
    int slot0 = blockIdx.x * 32;
    int b0 = blockIdx.x * 4;

    if (t < 32)  nodeS[t] = d_slotNode[slot0 + t];
    if (t < 128) b1s[t] = b1[t];
    if (t < RR)  b2s[t] = b2[t];
    __syncthreads();                               // nodeS ready

    {   // stage Ag: rows 0..3 = gf[b0..b0+3], rows 4..15 = 0  (512 float4)
        const float4* gf4 = (const float4*)gf;
        const float4 z = make_float4(0.f, 0.f, 0.f, 0.f);
#pragma unroll
        for (int i = t; i < 512; i += 128) {
            int row = i >> 5, c = i & 31;
            float4 v = (row < 4) ? gf4[(b0 + row) * 32 + c] : z;
            __nv_bfloat162 p0 = __floats2bfloat162_rn(v.x, v.y);
            __nv_bfloat162 p1 = __floats2bfloat162_rn(v.z, v.w);
            uint2 pk;
            pk.x = *reinterpret_cast<unsigned int*>(&p0);
            pk.y = *reinterpret_cast<unsigned int*>(&p1);
            *(uint2*)(Ag + row * 136 + c * 4) = pk;
        }
        // gather As: node rows (zeros for empty slots) (1024 float4)
        const float4* nf4 = (const float4*)nf;
#pragma unroll
        for (int i = t; i < 1024; i += 128) {
            int row = i >> 5, c = i & 31;
            int nd = nodeS[row];
            float4 v = (nd >= 0) ? nf4[nd * 32 + c] : z;
            __nv_bfloat162 p0 = __floats2bfloat162_rn(v.x, v.y);
            __nv_bfloat162 p1 = __floats2bfloat162_rn(v.z, v.w);
            uint2 pk;
            pk.x = *reinterpret_cast<unsigned int*>(&p0);
            pk.y = *reinterpret_cast<unsigned int*>(&p1);
            *(uint2*)(As + row * 136 + c * 4) = pk;
        }
    }
    __syncthreads();

    // ---- global mini-GEMM: GP(16x128) = Ag(16x128) @ w1[128:256] ----
    {
        wmma::fragment<wmma::matrix_a, 16, 16, 16, __nv_bfloat16, wmma::row_major> ga;
        wmma::fragment<wmma::matrix_b, 16, 16, 16, __nv_bfloat16, wmma::row_major> gb;
        wmma::fragment<wmma::accumulator, 16, 16, 16, float> gc[2];
#pragma unroll
        for (int n = 0; n < 2; n++) wmma::fill_fragment(gc[n], 0.f);
#pragma unroll
        for (int k = 0; k < 8; k++) {
            wmma::load_matrix_sync(ga, Ag + 16 * k, 136);
#pragma unroll
            for (int n = 0; n < 2; n++) {
                int nt = 2 * w + n;
                wmma::load_matrix_sync(gb, d_w1t + ((8 + k) * 8 + nt) * 256, 16);
                wmma::mma_sync(gc[n], ga, gb, gc[n]);
            }
        }
#pragma unroll
        for (int n = 0; n < 2; n++)
            wmma::store_matrix_sync(GP + 16 * (2 * w + n), gc[n], 132,
                                    wmma::mem_row_major);
    }

    // ---- node GEMM: Hn(32x128) = As(32x128) @ w1[0:128] ----
    wmma::fragment<wmma::matrix_a, 16, 16, 16, __nv_bfloat16, wmma::row_major> fa[2];
    wmma::fragment<wmma::matrix_b, 16, 16, 16, __nv_bfloat16, wmma::row_major> fb;
    wmma::fragment<wmma::accumulator, 16, 16, 16, float> fc[2][2];
#pragma unroll
    for (int mt = 0; mt < 2; mt++)
#pragma unroll
        for (int n = 0; n < 2; n++) wmma::fill_fragment(fc[mt][n], 0.f);

#pragma unroll
    for (int k = 0; k < 8; k++) {
#pragma unroll
        for (int mt = 0; mt < 2; mt++)
            wmma::load_matrix_sync(fa[mt], As + mt * 16 * 136 + 16 * k, 136);
#pragma unroll
        for (int n = 0; n < 2; n++) {
            int nt = 2 * w + n;
            wmma::load_matrix_sync(fb, d_w1t + (k * 8 + nt) * 256, 16);
#pragma unroll
            for (int mt = 0; mt < 2; mt++)
                wmma::mma_sync(fc[mt][n], fa[mt], fb, fc[mt][n]);
        }
    }
    __syncthreads();                               // As/Ag dead -> H32 aliases
#pragma unroll
    for (int mt = 0; mt < 2; mt++)
#pragma unroll
        for (int n = 0; n < 2; n++)
            wmma::store_matrix_sync(H32 + mt * 16 * 132 + 16 * (2 * w + n),
                                    fc[mt][n], 132, wmma::mem_row_major);
    __syncthreads();                               // full H + GP visible

    // ---- relu(H + b1 + GP[batch]) in place, fp32 ----
    {
        int row = t >> 2, q = t & 3;               // row 0..31, quarter 0..3
        float4* hr = (float4*)(H32 + row * 132 + q * 32);
        const float4* br = (const float4*)(b1s + q * 32);
        const float4* gr = (const float4*)(GP + (row >> 3) * 132 + q * 32);
#pragma unroll
        for (int j = 0; j < 8; j++) {
            float4 h = hr[j], g = br[j], p = gr[j];
            h.x = fmaxf(h.x + g.x + p.x, 0.f);
            h.y = fmaxf(h.y + g.y + p.y, 0.f);
            h.z = fmaxf(h.z + g.z + p.z, 0.f);
            h.w = fmaxf(h.w + g.w + p.w, 0.f);
            hr[j] = h;
        }
    }
    __syncthreads();

    // ---- layer 2 (tf32), warps 0..1: Sc(16x16) = H(16x128) @ d_w2f ----
    if (w < 2) {
        wmma::fragment<wmma::matrix_a, 16, 16, 8, wmma::precision::tf32, wmma::row_major> fa2;
        wmma::fragment<wmma::matrix_b, 16, 16, 8, wmma::precision::tf32, wmma::row_major> fb2;
        wmma::fragment<wmma::accumulator, 16, 16, 8, float> fc2;
        wmma::fill_fragment(fc2, 0.f);
#pragma unroll
        for (int k = 0; k < 16; k++) {
            wmma::load_matrix_sync(fa2, H32 + 16 * w * 132 + 8 * k, 132);
            wmma::load_matrix_sync(fb2, d_w2f + 8 * k * 16, 16);
#pragma unroll
            for (int i = 0; i < fa2.num_elements; i++)
                fa2.x[i] = wmma::__float_to_tf32(fa2.x[i]);
#pragma unroll
            for (int i = 0; i < fb2.num_elements; i++)
                fb2.x[i] = wmma::__float_to_tf32(fb2.x[i]);
            wmma::mma_sync(fc2, fa2, fb2, fc2);
        }
        wmma::store_matrix_sync(Sc + 16 * w * 16, fc2, 16, wmma::mem_row_major);
    }
    __syncthreads();

    // ---- masked output: 224 outputs over 128 threads ----
    for (int idx = t; idx < 32 * RR; idx += 128) {
        int m = idx / RR, r = idx - m * RR;
        int bb = b0 + (m >> 3);
        int orow = bb * (GG * RR) + (m & 7) * RR;
        float v = NEGV;
        if (nodeS[m] >= 0 && mvm[orow + r] != 0)
            v = Sc[m * 16 + r] + b2s[r];
        out[orow + r] = v;
    }
}

// ---------------- launch ---------------------------------------------------
extern "C" void kernel_launch(void* const* d_in, const int* in_sizes, int n_in,
                              void* d_out, int out_size) {
    const float* nf    = (const float*)d_in[0];
    const float* gf    = (const float*)d_in[1];
    const int*   gmask = (const int*)d_in[2];
    const int*   mvm   = (const int*)d_in[3];
    const int*   batch = (const int*)d_in[4];
    const float* w1    = (const float*)d_in[5];
    const float* b1    = (const float*)d_in[6];
    const float* w2    = (const float*)d_in[7];
    const float* b2    = (const float*)d_in[8];
    float*       out   = (float*)d_out;

    cudaFuncSetAttribute(k_main, cudaFuncAttributeMaxDynamicSharedMemorySize,
                         MAIN_SMEM_BYTES);

    k_front<<<FGRID, 256>>>(gmask, batch, w1, w2);
    k_main<<<1024, 128, MAIN_SMEM_BYTES>>>(nf, gf, b1, b2, mvm, out);
}

// round 12
// speedup vs baseline: 1.6016x; 1.6016x over previous
#include <cuda_runtime.h>
#include <cuda_bf16.h>
#include <cstdint>

// ManeuverHead on GB300 — 2 kernels, raw mma.sync (PTX) pipeline.
//  k_front: persistent fused front end (grid barriers): init + masked scans +
//           boundary cbase + scatter + w1/w2 staged in EXACT mma fragment order.
//  k_main : 512 blocks x 128 threads; each warp fully owns 16 slots (2 batches):
//           gather -> ldmatrix -> 256x mma.m16n8k16 (bf16, K=256) -> in-register
//           relu+b1 -> layer-2 mma (bf16) -> masked STG. No __syncthreads.
// N=262144, B=4096, D=128, G=8, R=7.

#define NNODES   262144
#define NB       4096
#define GG       8
#define RR       7
#define NSLOTS   (NB * GG)
#define NEGV     (-1e9f)
#define FGRID    256

// ---------------- device scratch ------------------------------------------
__device__ int          d_blockSums[FGRID];
__device__ int          d_blockOff[FGRID];
__device__ int          d_cbase[NB];
__device__ int          d_slotNode[NSLOTS];
__device__ uint2        d_w1frag[8192];   // 256 tiles (kt 0..15, nt 0..15) x 32 lanes
__device__ uint2        d_w2frag[256];    // 8 k-tiles x 32 lanes (w2 padded to 8 cols)
__device__ unsigned int g_cnt;            // zero-init
__device__ volatile unsigned int g_gen;   // zero-init

__device__ __forceinline__ unsigned int pk_bf2(float x, float y) {
    __nv_bfloat162 p = __floats2bfloat162_rn(x, y);
    return *reinterpret_cast<unsigned int*>(&p);
}

// ---------------- K1: fused front end --------------------------------------
__global__ void __launch_bounds__(256)
k_front(const int* __restrict__ mask, const int* __restrict__ batch,
        const float* __restrict__ w1, const float* __restrict__ w2) {
    int t = threadIdx.x, bid = blockIdx.x;
    int lane = t & 31, warp = t >> 5;
    int gid = bid * 256 + t;

    __shared__ int ws[8];
    __shared__ unsigned int s_gen;
    __shared__ int s_lead;

    // ---- P0: aux init + fragment-order weight staging ----
    if (gid < NSLOTS) d_slotNode[gid] = -1;
    if (gid < 8192) {                       // w1 fragments (m16n8k16 B layout)
        int tile = gid >> 5, fl = gid & 31;
        int kt = tile >> 4, nt = tile & 15;
        int q = fl & 3, g = fl >> 2;
        int k0 = kt * 16 + 2 * q;
        int n  = nt * 8 + g;
        uint2 v;
        v.x = pk_bf2(w1[k0 * 128 + n],        w1[(k0 + 1) * 128 + n]);
        v.y = pk_bf2(w1[(k0 + 8) * 128 + n],  w1[(k0 + 9) * 128 + n]);
        d_w1frag[gid] = v;
    }
    if (gid < 256) {                        // w2 fragments (padded to 8 cols)
        int kt2 = gid >> 5, fl = gid & 31;
        int q = fl & 3, g = fl >> 2;
        int k0 = kt2 * 16 + 2 * q;
        float w00 = (g < RR) ? w2[k0 * RR + g]       : 0.f;
        float w01 = (g < RR) ? w2[(k0 + 1) * RR + g] : 0.f;
        float w10 = (g < RR) ? w2[(k0 + 8) * RR + g] : 0.f;
        float w11 = (g < RR) ? w2[(k0 + 9) * RR + g] : 0.f;
        uint2 v;
        v.x = pk_bf2(w00, w01);
        v.y = pk_bf2(w10, w11);
        d_w2frag[gid] = v;
    }

    // ---- P0: block scan of masked flags ----
    int4 m = ((const int4*)mask)[gid];
    int4 b = ((const int4*)batch)[gid];
    int g0 = m.x != 0, g1 = m.y != 0, g2 = m.z != 0, g3 = m.w != 0;
    int s = g0 + g1 + g2 + g3;
    int inc = s;
#pragma unroll
    for (int o = 1; o < 32; o <<= 1) {
        int v = __shfl_up_sync(~0u, inc, o);
        if (lane >= o) inc += v;
    }
    if (lane == 31) ws[warp] = inc;
    __syncthreads();
    if (warp == 0 && lane < 8) {
        int v = ws[lane], iv = v;
#pragma unroll
        for (int o = 1; o < 8; o <<= 1) {
            int x = __shfl_up_sync(0xffu, iv, o);
            if (lane >= o) iv += x;
        }
        ws[lane] = iv - v;
        if (lane == 7) d_blockSums[bid] = iv;
    }
    __syncthreads();
    int lexcl = ws[warp] + (inc - s);

    // ---- BAR1: leader scans blockSums -> blockOff ----
    __threadfence();
    __syncthreads();
    if (t == 0) {
        s_gen = g_gen;
        unsigned int a = atomicAdd(&g_cnt, 1u);
        s_lead = (a == (unsigned)gridDim.x - 1u);
    }
    __syncthreads();
    if (s_lead) {
        __threadfence();
        int v = d_blockSums[t];
        int iv = v;
#pragma unroll
        for (int o = 1; o < 32; o <<= 1) {
            int x = __shfl_up_sync(~0u, iv, o);
            if (lane >= o) iv += x;
        }
        if (lane == 31) ws[warp] = iv;
        __syncthreads();
        if (warp == 0 && lane < 8) {
            int v2 = ws[lane], iv2 = v2;
#pragma unroll
            for (int o = 1; o < 8; o <<= 1) {
                int x = __shfl_up_sync(0xffu, iv2, o);
                if (lane >= o) iv2 += x;
            }
            ws[lane] = iv2 - v2;
        }
        __syncthreads();
        d_blockOff[t] = ws[warp] + (iv - v);
        __threadfence();
        __syncthreads();
        if (t == 0) {
            *(volatile unsigned int*)&g_cnt = 0u;
            __threadfence();
            g_gen = s_gen + 1u;
        }
    } else {
        if (t == 0) {
            while (g_gen == s_gen) __nanosleep(64);
            __threadfence();
        }
        __syncthreads();
    }

    // ---- P2: boundary nodes write cbase ----
    int pe0 = d_blockOff[bid] + lexcl;
    int pw = __shfl_up_sync(~0u, b.w, 1);
    int prevb = (lane == 0) ? ((gid > 0) ? batch[gid * 4 - 1] : -1) : pw;
    {
        int pe = pe0;
        if (b.x != prevb) d_cbase[b.x] = pe;  pe += g0;
        if (b.y != b.x)   d_cbase[b.y] = pe;  pe += g1;
        if (b.z != b.y)   d_cbase[b.z] = pe;  pe += g2;
        if (b.w != b.z)   d_cbase[b.w] = pe;
    }

    // ---- BAR2 ----
    __threadfence();
    __syncthreads();
    if (t == 0) {
        s_gen = g_gen;
        unsigned int a = atomicAdd(&g_cnt, 1u);
        s_lead = (a == (unsigned)gridDim.x - 1u);
    }
    __syncthreads();
    if (s_lead) {
        if (t == 0) {
            *(volatile unsigned int*)&g_cnt = 0u;
            __threadfence();
            g_gen = s_gen + 1u;
        }
        __syncthreads();
    } else {
        if (t == 0) {
            while (g_gen == s_gen) __nanosleep(64);
            __threadfence();
        }
        __syncthreads();
    }

    // ---- P3: scatter ----
    int base = gid * 4;
    int pre = pe0;
    if (g0) { int r = pre - d_cbase[b.x]; if (r < GG) d_slotNode[b.x * GG + r] = base;     pre++; }
    if (g1) { int r = pre - d_cbase[b.y]; if (r < GG) d_slotNode[b.y * GG + r] = base + 1; pre++; }
    if (g2) { int r = pre - d_cbase[b.z]; if (r < GG) d_slotNode[b.z * GG + r] = base + 2; pre++; }
    if (g3) { int r = pre - d_cbase[b.w]; if (r < GG) d_slotNode[b.w * GG + r] = base + 3; }
}

// ---------------- K2: main — warp-autonomous mma.sync pipeline --------------
// 512 blocks x 128 threads (4 warps). Warp strip: 16 rows x 264 bf16 (528 B
// row stride -> ldmatrix conflict-free), cols 0..127 node feats, 128..255
// globals. Per warp: 16 kt x (ldmatrix.x4 + 16 x (LDG.64 fb + mma)), then
// 8 x (in-register relu+b1 -> bf16 -> layer-2 mma), masked STG.
#define STRIP_BYTES 8448
#define MAIN_SMEM_BYTES (4 * STRIP_BYTES)

__device__ __forceinline__ void mma16816(float& c0, float& c1, float& c2, float& c3,
                                         unsigned a0, unsigned a1, unsigned a2, unsigned a3,
                                         unsigned b0, unsigned b1) {
    asm volatile(
        "mma.sync.aligned.m16n8k16.row.col.f32.bf16.bf16.f32 "
        "{%0,%1,%2,%3}, {%4,%5,%6,%7}, {%8,%9}, {%0,%1,%2,%3};"
        : "+f"(c0), "+f"(c1), "+f"(c2), "+f"(c3)
        : "r"(a0), "r"(a1), "r"(a2), "r"(a3), "r"(b0), "r"(b1));
}

__global__ void __launch_bounds__(128, 4)
k_main(const float* __restrict__ nf,
       const float* __restrict__ gf,
       const float* __restrict__ b1,
       const float* __restrict__ b2,
       const int* __restrict__ mvm,
       float* __restrict__ out) {
    extern __shared__ __align__(16) unsigned char sm[];
    int t = threadIdx.x, w = t >> 5, lane = t & 31;
    unsigned char* strip = sm + w * STRIP_BYTES;

    int slot0 = (blockIdx.x * 4 + w) * 16;
    int b0w   = (blockIdx.x * 4 + w) * 2;          // 2 batches per warp

    int nd = (lane < 16) ? d_slotNode[slot0 + lane] : -1;

    // ---- gather: 16 rows x 64 float4-units (256 cols) -> bf16 strip ----
    {
        const float4* nf4 = (const float4*)nf;
        const float4* gf4 = (const float4*)gf;
        const float4 z = make_float4(0.f, 0.f, 0.f, 0.f);
#pragma unroll
        for (int i = lane; i < 1024; i += 32) {
            int row = i >> 6, c4 = i & 63;
            float4 v;
            if (c4 < 32) {
                int ndr = __shfl_sync(~0u, nd, row);
                v = (ndr >= 0) ? nf4[ndr * 32 + c4] : z;
            } else {
                v = gf4[(b0w + (row >> 3)) * 32 + (c4 - 32)];
            }
            uint2 pk;
            pk.x = pk_bf2(v.x, v.y);
            pk.y = pk_bf2(v.z, v.w);
            *(uint2*)(strip + row * 528 + c4 * 8) = pk;
        }
    }
    __syncwarp();

    // ---- layer 1: C[nt] (nt=0..15) = A(16x256) @ w1 fragments ----
    unsigned int smaddr;
    {
        unsigned long long p = (unsigned long long)(strip);
        asm("{ .reg .u64 tt; cvta.to.shared.u64 tt, %1; cvt.u32.u64 %0, tt; }"
            : "=r"(smaddr) : "l"(strip));
    }
    unsigned int lmrow = (lane & 7) + ((lane >> 3) & 1) * 8;
    unsigned int lmaddr = smaddr + lmrow * 528 + (lane >> 4) * 16;

    float c[16][4];
#pragma unroll
    for (int nt = 0; nt < 16; nt++)
#pragma unroll
        for (int j = 0; j < 4; j++) c[nt][j] = 0.f;

#pragma unroll 1
    for (int kt = 0; kt < 16; kt++) {
        unsigned a0, a1, a2, a3;
        asm volatile("ldmatrix.sync.aligned.m8n8.x4.shared.b16 {%0,%1,%2,%3}, [%4];"
                     : "=r"(a0), "=r"(a1), "=r"(a2), "=r"(a3)
                     : "r"(lmaddr + kt * 32));
        const uint2* fb = d_w1frag + kt * 16 * 32 + lane;
#pragma unroll
        for (int nt = 0; nt < 16; nt++) {
            uint2 bv = fb[nt * 32];
            mma16816(c[nt][0], c[nt][1], c[nt][2], c[nt][3],
                     a0, a1, a2, a3, bv.x, bv.y);
        }
    }

    // ---- layer 2: in-register relu+b1 -> bf16 A fragments -> mma ----
    int q = lane & 3, g = lane >> 2;
    float d0 = 0.f, d1 = 0.f, d2 = 0.f, d3 = 0.f;
#pragma unroll
    for (int k2 = 0; k2 < 8; k2++) {
        float2 ba = *(const float2*)(b1 + k2 * 16 + 2 * q);
        float2 bb = *(const float2*)(b1 + k2 * 16 + 8 + 2 * q);
        unsigned A0 = pk_bf2(fmaxf(c[2 * k2][0] + ba.x, 0.f),
                             fmaxf(c[2 * k2][1] + ba.y, 0.f));
        unsigned A1 = pk_bf2(fmaxf(c[2 * k2][2] + ba.x, 0.f),
                             fmaxf(c[2 * k2][3] + ba.y, 0.f));
        unsigned A2 = pk_bf2(fmaxf(c[2 * k2 + 1][0] + bb.x, 0.f),
                             fmaxf(c[2 * k2 + 1][1] + bb.y, 0.f));
        unsigned A3 = pk_bf2(fmaxf(c[2 * k2 + 1][2] + bb.x, 0.f),
                             fmaxf(c[2 * k2 + 1][3] + bb.y, 0.f));
        uint2 bv = d_w2frag[k2 * 32 + lane];
        mma16816(d0, d1, d2, d3, A0, A1, A2, A3, bv.x, bv.y);
    }

    // ---- masked output: fc2 c0,c1 = row g cols 2q,2q+1; c2,c3 = row g+8 ----
    {
        int r0c = 2 * q, r1c = 2 * q + 1;
        float b2v0 = b2[r0c];                       // r0c in {0,2,4,6} < 7
        float b2v1 = (r1c < RR) ? b2[r1c] : 0.f;
#pragma unroll
        for (int half = 0; half < 2; half++) {
            int m = g + half * 8;
            float v0 = half ? d2 : d0;
            float v1 = half ? d3 : d1;
            int occ = __shfl_sync(~0u, nd, m) >= 0;
            int bb2 = b0w + (m >> 3);
            int orow = bb2 * (GG * RR) + (m & 7) * RR;
            out[orow + r0c] = (occ && mvm[orow + r0c] != 0) ? v0 + b2v0 : NEGV;
            if (r1c < RR)
                out[orow + r1c] = (occ && mvm[orow + r1c] != 0) ? v1 + b2v1 : NEGV;
        }
    }
}

// ---------------- launch ---------------------------------------------------
extern "C" void kernel_launch(void* const* d_in, const int* in_sizes, int n_in,
                              void* d_out, int out_size) {
    const float* nf    = (const float*)d_in[0];
    const float* gf    = (const float*)d_in[1];
    const int*   gmask = (const int*)d_in[2];
    const int*   mvm   = (const int*)d_in[3];
    const int*   batch = (const int*)d_in[4];
    const float* w1    = (const float*)d_in[5];
    const float* b1    = (const float*)d_in[6];
    const float* w2    = (const float*)d_in[7];
    const float* b2    = (const float*)d_in[8];
    float*       out   = (float*)d_out;

    cudaFuncSetAttribute(k_main, cudaFuncAttributeMaxDynamicSharedMemorySize,
                         MAIN_SMEM_BYTES);

    k_front<<<FGRID, 256>>>(gmask, batch, w1, w2);
    k_main<<<512, 128, MAIN_SMEM_BYTES>>>(nf, gf, b1, b2, mvm, out);
}